// round 3
// baseline (speedup 1.0000x reference)
#include <cuda_runtime.h>
#include <cuda_fp16.h>
#include <cstdint>
#include <cstddef>

#define IN_F   4096
#define OUT_F  4096
#define MTOT   8192   // 4 * 2048

// ---------------- scratch (static device globals: allocation-free) -----------
__device__ __half g_Xh[(size_t)MTOT * IN_F];   // x in fp16           (64 MiB)
__device__ __half g_Wh[(size_t)OUT_F * IN_F];  // W_eff in fp16       (32 MiB)

// ---------------- PTX helpers ----------------
__device__ __forceinline__ uint32_t smem_u32(const void* p) {
    uint32_t r;
    asm("{ .reg .u64 t; cvta.to.shared.u64 t, %1; cvt.u32.u64 %0, t; }"
        : "=r"(r) : "l"(p));
    return r;
}
__device__ __forceinline__ void cp_async16(uint32_t dst, const void* src) {
    asm volatile("cp.async.cg.shared.global [%0], [%1], 16;" :: "r"(dst), "l"(src));
}
#define CP_COMMIT() asm volatile("cp.async.commit_group;" ::: "memory")
#define CP_WAIT(n)  asm volatile("cp.async.wait_group %0;" :: "n"(n) : "memory")

__device__ __forceinline__ void ldsm_x4(uint32_t* r, uint32_t addr) {
    asm volatile("ldmatrix.sync.aligned.m8n8.x4.shared.b16 {%0,%1,%2,%3}, [%4];"
                 : "=r"(r[0]), "=r"(r[1]), "=r"(r[2]), "=r"(r[3]) : "r"(addr));
}
__device__ __forceinline__ void mma16816(float* c, const uint32_t* a, const uint32_t* b) {
    asm volatile(
        "mma.sync.aligned.m16n8k16.row.col.f32.f16.f16.f32 "
        "{%0,%1,%2,%3}, {%4,%5,%6,%7}, {%8,%9}, {%0,%1,%2,%3};"
        : "+f"(c[0]), "+f"(c[1]), "+f"(c[2]), "+f"(c[3])
        : "r"(a[0]), "r"(a[1]), "r"(a[2]), "r"(a[3]), "r"(b[0]), "r"(b[1]));
}

// ---------------- kernel 1: x fp32 -> fp16 ----------------
__global__ void k_convert_x(const float4* __restrict__ x) {
    const int n4 = MTOT * IN_F / 4;
    uint2* __restrict__ out = reinterpret_cast<uint2*>(g_Xh);
    int stride = gridDim.x * blockDim.x;
    for (int i = blockIdx.x * blockDim.x + threadIdx.x; i < n4; i += stride) {
        float4 v = x[i];
        __half2 lo = __floats2half2_rn(v.x, v.y);
        __half2 hi = __floats2half2_rn(v.z, v.w);
        uint2 o;
        o.x = *reinterpret_cast<uint32_t*>(&lo);
        o.y = *reinterpret_cast<uint32_t*>(&hi);
        out[i] = o;
    }
}

// ---------------- kernel 2: W_eff = dequant + LoRA fold -> fp16 --------------
#define TO 32
#define TI 512
__global__ void k_fold_w(const int* __restrict__ qw, const float* __restrict__ qs,
                         const float* __restrict__ A, const float* __restrict__ B) {
    __shared__ float As[16][TI + 4];
    __shared__ float Bs[TO][16];
    __shared__ float Ss[TO];
    const int tid = threadIdx.x;                  // 256
    const int o0 = blockIdx.x * TO;
    // FIX: TO*16 = 512 entries, only 256 threads -> strided loop (was if(tid<512))
    for (int t = tid; t < TO * 16; t += 256)
        Bs[t / 16][t % 16] = B[(size_t)(o0 + t / 16) * 16 + (t % 16)];
    if (tid < TO) Ss[tid] = qs[o0 + tid];
    const int ro = tid >> 3;    // row 0..31
    const int l8 = tid & 7;     // 0..7
    for (int cb = 0; cb < IN_F; cb += TI) {
        __syncthreads();
        for (int t = tid; t < 16 * (TI / 4); t += 256) {
            int r = t / (TI / 4), j = t % (TI / 4);
            float4 v = reinterpret_cast<const float4*>(A + (size_t)r * IN_F + cb)[j];
            *reinterpret_cast<float4*>(&As[r][j * 4]) = v;
        }
        __syncthreads();
        const float s = Ss[ro];
        const float* brow = Bs[ro];
        #pragma unroll 4
        for (int j = 0; j < TI / 32; ++j) {
            int il = l8 * 4 + j * 32;
            int4 q4 = *reinterpret_cast<const int4*>(&qw[(size_t)(o0 + ro) * IN_F + cb + il]);
            float a0 = q4.x * s, a1 = q4.y * s, a2 = q4.z * s, a3 = q4.w * s;
            #pragma unroll
            for (int r = 0; r < 16; ++r) {
                float b2 = 2.0f * brow[r];
                a0 = fmaf(b2, As[r][il + 0], a0);
                a1 = fmaf(b2, As[r][il + 1], a1);
                a2 = fmaf(b2, As[r][il + 2], a2);
                a3 = fmaf(b2, As[r][il + 3], a3);
            }
            __half2 h0 = __floats2half2_rn(a0, a1);
            __half2 h1 = __floats2half2_rn(a2, a3);
            uint2 o;
            o.x = *reinterpret_cast<uint32_t*>(&h0);
            o.y = *reinterpret_cast<uint32_t*>(&h1);
            *reinterpret_cast<uint2*>(&g_Wh[(size_t)(o0 + ro) * IN_F + cb + il]) = o;
        }
    }
}

// ---------------- kernel 3: pipelined mma.sync fp16 GEMM ----------------
// BM=128, BN=256, BK=64 (128B rows, chunk^(row&7) swizzle), 3 stages.
// 8 warps as 2(m) x 4(n); warp tile 64x64; mma.sync.m16n8k16 f32<=f16.
#define BM 128
#define BN 256
#define BK 64
#define NSTAGES 3
#define A_BYTES (BM * 128)                 // 16384
#define B_BYTES (BN * 128)                 // 32768
#define STAGE_BYTES (A_BYTES + B_BYTES)    // 49152
#define GEMM_SMEM (NSTAGES * STAGE_BYTES)  // 147456
#define GEMM_THREADS 256
#define KCH (IN_F / BK)                    // 64

__device__ __forceinline__ void load_stage(uint32_t sb, int slot, int c,
                                           const __half* ga_base, const __half* gb_base,
                                           int tid) {
    uint32_t abase = sb + slot * STAGE_BYTES;
    uint32_t bbase = abase + A_BYTES;
    const __half* ga = ga_base + c * BK;
    const __half* gb = gb_base + c * BK;
    #pragma unroll
    for (int it = 0; it < (BM + BN) * 8 / GEMM_THREADS; ++it) {   // 12
        int t = tid + it * GEMM_THREADS;
        int chunk = t & 7;
        int row = (t >> 3);
        if (t < BM * 8) {
            uint32_t off = (uint32_t)(row * 128 + ((chunk ^ (row & 7)) << 4));
            cp_async16(abase + off, ga + (size_t)row * IN_F + chunk * 8);
        } else {
            row -= BM;
            uint32_t off = (uint32_t)(row * 128 + ((chunk ^ (row & 7)) << 4));
            cp_async16(bbase + off, gb + (size_t)row * IN_F + chunk * 8);
        }
    }
}

__global__ void __launch_bounds__(GEMM_THREADS, 1)
k_gemm(const float* __restrict__ bias, float* __restrict__ out) {
    extern __shared__ char smem[];
    uint32_t sb = smem_u32(smem);
    const int tid = threadIdx.x;
    const int wid = tid >> 5, lid = tid & 31;
    const int wm = wid & 1;          // 0..1
    const int wn = wid >> 1;         // 0..3
    const int m0 = blockIdx.y * BM;
    const int n0 = blockIdx.x * BN;
    const __half* ga_base = g_Xh + (size_t)m0 * IN_F;
    const __half* gb_base = g_Wh + (size_t)n0 * IN_F;

    float ac[4][8][4];
    #pragma unroll
    for (int i = 0; i < 4; ++i)
        #pragma unroll
        for (int j = 0; j < 8; ++j)
            #pragma unroll
            for (int k = 0; k < 4; ++k) ac[i][j][k] = 0.0f;

    // prologue: stages 0,1
    load_stage(sb, 0, 0, ga_base, gb_base, tid); CP_COMMIT();
    load_stage(sb, 1, 1, ga_base, gb_base, tid); CP_COMMIT();

    int slot = 0;
    for (int c = 0; c < KCH; ++c) {
        CP_WAIT(1);
        __syncthreads();
        if (c + 2 < KCH) {
            int nslot = slot + 2; if (nslot >= NSTAGES) nslot -= NSTAGES;
            load_stage(sb, nslot, c + 2, ga_base, gb_base, tid);
        }
        CP_COMMIT();

        uint32_t Ab = sb + slot * STAGE_BYTES;
        uint32_t Bb = Ab + A_BYTES;
        #pragma unroll
        for (int ks = 0; ks < BK / 16; ++ks) {
            uint32_t af[4][4], bf[4][4];
            #pragma unroll
            for (int i = 0; i < 4; ++i) {
                int row = wm * 64 + i * 16 + (lid & 15);
                int chunk = ks * 2 + (lid >> 4);
                uint32_t addr = Ab + (uint32_t)(row * 128) + (((chunk ^ (row & 7)) & 7) << 4);
                ldsm_x4(af[i], addr);
            }
            #pragma unroll
            for (int j = 0; j < 4; ++j) {
                int row = wn * 64 + j * 16 + ((lid >> 4) << 3) + (lid & 7);
                int chunk = ks * 2 + ((lid >> 3) & 1);
                uint32_t addr = Bb + (uint32_t)(row * 128) + (((chunk ^ (row & 7)) & 7) << 4);
                ldsm_x4(bf[j], addr);
            }
            #pragma unroll
            for (int i = 0; i < 4; ++i) {
                #pragma unroll
                for (int jj = 0; jj < 8; ++jj) {
                    mma16816(ac[i][jj], af[i], &bf[jj >> 1][(jj & 1) * 2]);
                }
            }
        }
        ++slot; if (slot >= NSTAGES) slot -= NSTAGES;
    }

    // epilogue: write 64x64 warp tile with bias
    const int mbase = m0 + wm * 64 + (lid >> 2);
    const int nbase = n0 + wn * 64 + (lid & 3) * 2;
    #pragma unroll
    for (int i = 0; i < 4; ++i) {
        #pragma unroll
        for (int jj = 0; jj < 8; ++jj) {
            int n = nbase + jj * 8;
            float b0 = bias[n], b1 = bias[n + 1];
            int m = mbase + i * 16;
            float2 v0 = make_float2(ac[i][jj][0] + b0, ac[i][jj][1] + b1);
            float2 v1 = make_float2(ac[i][jj][2] + b0, ac[i][jj][3] + b1);
            *reinterpret_cast<float2*>(&out[(size_t)m * OUT_F + n]) = v0;
            *reinterpret_cast<float2*>(&out[(size_t)(m + 8) * OUT_F + n]) = v1;
        }
    }
}

// ---------------- launcher ----------------
extern "C" void kernel_launch(void* const* d_in, const int* in_sizes, int n_in,
                              void* d_out, int out_size) {
    const float* x    = (const float*)d_in[0];
    const int*   qw   = (const int*)  d_in[1];
    const float* qs   = (const float*)d_in[2];
    const float* bias = (const float*)d_in[3];
    const float* lA   = (const float*)d_in[4];
    const float* lB   = (const float*)d_in[5];
    float* out = (float*)d_out;

    cudaFuncSetAttribute(k_gemm, cudaFuncAttributeMaxDynamicSharedMemorySize, GEMM_SMEM);

    k_convert_x<<<4096, 256>>>(reinterpret_cast<const float4*>(x));
    k_fold_w<<<OUT_F / TO, 256>>>(qw, qs, lA, lB);
    k_gemm<<<dim3(OUT_F / BN, MTOT / BM), GEMM_THREADS, GEMM_SMEM>>>(bias, out);
}

// round 4
// speedup vs baseline: 1.0205x; 1.0205x over previous
#include <cuda_runtime.h>
#include <cuda_fp16.h>
#include <cstdint>
#include <cstddef>

#define IN_F   4096
#define OUT_F  4096
#define MTOT   8192   // 4 * 2048

// ---------------- scratch (static device globals: allocation-free) -----------
__device__ __half g_Xh[(size_t)MTOT * IN_F];   // x in fp16           (64 MiB)
__device__ __half g_Wh[(size_t)OUT_F * IN_F];  // W_eff in fp16       (32 MiB)

// ---------------- PTX helpers ----------------
__device__ __forceinline__ uint32_t smem_u32(const void* p) {
    uint32_t r;
    asm("{ .reg .u64 t; cvta.to.shared.u64 t, %1; cvt.u32.u64 %0, t; }"
        : "=r"(r) : "l"(p));
    return r;
}
__device__ __forceinline__ void cp_async16(uint32_t dst, const void* src) {
    asm volatile("cp.async.cg.shared.global [%0], [%1], 16;" :: "r"(dst), "l"(src));
}
#define CP_COMMIT() asm volatile("cp.async.commit_group;" ::: "memory")
#define CP_WAIT(n)  asm volatile("cp.async.wait_group %0;" :: "n"(n) : "memory")

__device__ __forceinline__ void ldsm_x4(uint32_t* r, uint32_t addr) {
    asm volatile("ldmatrix.sync.aligned.m8n8.x4.shared.b16 {%0,%1,%2,%3}, [%4];"
                 : "=r"(r[0]), "=r"(r[1]), "=r"(r[2]), "=r"(r[3]) : "r"(addr));
}
__device__ __forceinline__ void mma16816(float* c, const uint32_t* a, const uint32_t* b) {
    asm volatile(
        "mma.sync.aligned.m16n8k16.row.col.f32.f16.f16.f32 "
        "{%0,%1,%2,%3}, {%4,%5,%6,%7}, {%8,%9}, {%0,%1,%2,%3};"
        : "+f"(c[0]), "+f"(c[1]), "+f"(c[2]), "+f"(c[3])
        : "r"(a[0]), "r"(a[1]), "r"(a[2]), "r"(a[3]), "r"(b[0]), "r"(b[1]));
}

// ---------------- kernel 1: x fp32 -> fp16 ----------------
__global__ void k_convert_x(const float4* __restrict__ x) {
    const int n4 = MTOT * IN_F / 4;
    uint2* __restrict__ out = reinterpret_cast<uint2*>(g_Xh);
    int stride = gridDim.x * blockDim.x;
    for (int i = blockIdx.x * blockDim.x + threadIdx.x; i < n4; i += stride) {
        float4 v = x[i];
        __half2 lo = __floats2half2_rn(v.x, v.y);
        __half2 hi = __floats2half2_rn(v.z, v.w);
        uint2 o;
        o.x = *reinterpret_cast<uint32_t*>(&lo);
        o.y = *reinterpret_cast<uint32_t*>(&hi);
        out[i] = o;
    }
}

// ---------------- kernel 2: W_eff = dequant + LoRA fold -> fp16 --------------
#define TO 32
#define TI 512
__global__ void k_fold_w(const int* __restrict__ qw, const float* __restrict__ qs,
                         const float* __restrict__ A, const float* __restrict__ B) {
    __shared__ float As[16][TI + 4];
    __shared__ float Bs[TO][16];
    __shared__ float Ss[TO];
    const int tid = threadIdx.x;                  // 256
    const int o0 = blockIdx.x * TO;
    for (int t = tid; t < TO * 16; t += 256)
        Bs[t / 16][t % 16] = B[(size_t)(o0 + t / 16) * 16 + (t % 16)];
    if (tid < TO) Ss[tid] = qs[o0 + tid];
    const int ro = tid >> 3;    // row 0..31
    const int l8 = tid & 7;     // 0..7
    for (int cb = 0; cb < IN_F; cb += TI) {
        __syncthreads();
        for (int t = tid; t < 16 * (TI / 4); t += 256) {
            int r = t / (TI / 4), j = t % (TI / 4);
            float4 v = reinterpret_cast<const float4*>(A + (size_t)r * IN_F + cb)[j];
            *reinterpret_cast<float4*>(&As[r][j * 4]) = v;
        }
        __syncthreads();
        const float s = Ss[ro];
        const float* brow = Bs[ro];
        #pragma unroll 4
        for (int j = 0; j < TI / 32; ++j) {
            int il = l8 * 4 + j * 32;
            int4 q4 = *reinterpret_cast<const int4*>(&qw[(size_t)(o0 + ro) * IN_F + cb + il]);
            float a0 = q4.x * s, a1 = q4.y * s, a2 = q4.z * s, a3 = q4.w * s;
            #pragma unroll
            for (int r = 0; r < 16; ++r) {
                float b2 = 2.0f * brow[r];
                a0 = fmaf(b2, As[r][il + 0], a0);
                a1 = fmaf(b2, As[r][il + 1], a1);
                a2 = fmaf(b2, As[r][il + 2], a2);
                a3 = fmaf(b2, As[r][il + 3], a3);
            }
            __half2 h0 = __floats2half2_rn(a0, a1);
            __half2 h1 = __floats2half2_rn(a2, a3);
            uint2 o;
            o.x = *reinterpret_cast<uint32_t*>(&h0);
            o.y = *reinterpret_cast<uint32_t*>(&h1);
            *reinterpret_cast<uint2*>(&g_Wh[(size_t)(o0 + ro) * IN_F + cb + il]) = o;
        }
    }
}

// ---------------- kernel 3: pipelined mma.sync fp16 GEMM ----------------
// BM=128, BN=256, BK=64 (128B rows, chunk^(row&7) swizzle), 4 stages.
// 16 warps as 2(m) x 8(n); warp tile 64x32; mma.sync.m16n8k16 f32<=f16.
#define BM 128
#define BN 256
#define BK 64
#define NSTAGES 4
#define A_BYTES (BM * 128)                 // 16384
#define B_BYTES (BN * 128)                 // 32768
#define STAGE_BYTES (A_BYTES + B_BYTES)    // 49152
#define GEMM_SMEM (NSTAGES * STAGE_BYTES)  // 196608
#define GEMM_THREADS 512
#define KCH (IN_F / BK)                    // 64

__device__ __forceinline__ void load_stage(uint32_t sb, int slot, int c,
                                           const __half* ga_base, const __half* gb_base,
                                           int tid) {
    uint32_t abase = sb + slot * STAGE_BYTES;
    uint32_t bbase = abase + A_BYTES;
    const __half* ga = ga_base + c * BK;
    const __half* gb = gb_base + c * BK;
    #pragma unroll
    for (int it = 0; it < (BM + BN) * 8 / GEMM_THREADS; ++it) {   // 6
        int t = tid + it * GEMM_THREADS;
        int chunk = t & 7;
        int row = (t >> 3);
        if (t < BM * 8) {
            uint32_t off = (uint32_t)(row * 128 + ((chunk ^ (row & 7)) << 4));
            cp_async16(abase + off, ga + (size_t)row * IN_F + chunk * 8);
        } else {
            row -= BM;
            uint32_t off = (uint32_t)(row * 128 + ((chunk ^ (row & 7)) << 4));
            cp_async16(bbase + off, gb + (size_t)row * IN_F + chunk * 8);
        }
    }
}

__global__ void __launch_bounds__(GEMM_THREADS, 1)
k_gemm(const float* __restrict__ bias, float* __restrict__ out) {
    extern __shared__ char smem[];
    uint32_t sb = smem_u32(smem);
    const int tid = threadIdx.x;
    const int wid = tid >> 5, lid = tid & 31;
    const int wm = wid & 1;          // 0..1  (m: 64-row halves)
    const int wn = wid >> 1;         // 0..7  (n: 32-col slices)
    const int m0 = blockIdx.y * BM;
    const int n0 = blockIdx.x * BN;
    const __half* ga_base = g_Xh + (size_t)m0 * IN_F;
    const __half* gb_base = g_Wh + (size_t)n0 * IN_F;

    float ac[4][4][4];
    #pragma unroll
    for (int i = 0; i < 4; ++i)
        #pragma unroll
        for (int j = 0; j < 4; ++j)
            #pragma unroll
            for (int k = 0; k < 4; ++k) ac[i][j][k] = 0.0f;

    // prologue: stages 0,1,2
    load_stage(sb, 0, 0, ga_base, gb_base, tid); CP_COMMIT();
    load_stage(sb, 1, 1, ga_base, gb_base, tid); CP_COMMIT();
    load_stage(sb, 2, 2, ga_base, gb_base, tid); CP_COMMIT();

    int slot = 0;
    for (int c = 0; c < KCH; ++c) {
        CP_WAIT(2);
        __syncthreads();
        if (c + 3 < KCH) {
            int nslot = slot + 3; if (nslot >= NSTAGES) nslot -= NSTAGES;
            load_stage(sb, nslot, c + 3, ga_base, gb_base, tid);
        }
        CP_COMMIT();

        uint32_t Ab = sb + slot * STAGE_BYTES;
        uint32_t Bb = Ab + A_BYTES;
        #pragma unroll
        for (int ks = 0; ks < BK / 16; ++ks) {
            uint32_t af[4][4], bf[2][4];
            #pragma unroll
            for (int i = 0; i < 4; ++i) {
                int row = wm * 64 + i * 16 + (lid & 15);
                int chunk = ks * 2 + (lid >> 4);
                uint32_t addr = Ab + (uint32_t)(row * 128) + (((chunk ^ (row & 7)) & 7) << 4);
                ldsm_x4(af[i], addr);
            }
            #pragma unroll
            for (int j = 0; j < 2; ++j) {
                int row = wn * 32 + j * 16 + ((lid >> 4) << 3) + (lid & 7);
                int chunk = ks * 2 + ((lid >> 3) & 1);
                uint32_t addr = Bb + (uint32_t)(row * 128) + (((chunk ^ (row & 7)) & 7) << 4);
                ldsm_x4(bf[j], addr);
            }
            #pragma unroll
            for (int i = 0; i < 4; ++i) {
                #pragma unroll
                for (int jj = 0; jj < 4; ++jj) {
                    mma16816(ac[i][jj], af[i], &bf[jj >> 1][(jj & 1) * 2]);
                }
            }
        }
        ++slot; if (slot >= NSTAGES) slot -= NSTAGES;
    }

    // epilogue: write 64x32 warp tile with bias
    const int mbase = m0 + wm * 64 + (lid >> 2);
    const int nbase = n0 + wn * 32 + (lid & 3) * 2;
    #pragma unroll
    for (int i = 0; i < 4; ++i) {
        #pragma unroll
        for (int jj = 0; jj < 4; ++jj) {
            int n = nbase + jj * 8;
            float b0 = bias[n], b1 = bias[n + 1];
            int m = mbase + i * 16;
            float2 v0 = make_float2(ac[i][jj][0] + b0, ac[i][jj][1] + b1);
            float2 v1 = make_float2(ac[i][jj][2] + b0, ac[i][jj][3] + b1);
            *reinterpret_cast<float2*>(&out[(size_t)m * OUT_F + n]) = v0;
            *reinterpret_cast<float2*>(&out[(size_t)(m + 8) * OUT_F + n]) = v1;
        }
    }
}

// ---------------- launcher ----------------
extern "C" void kernel_launch(void* const* d_in, const int* in_sizes, int n_in,
                              void* d_out, int out_size) {
    const float* x    = (const float*)d_in[0];
    const int*   qw   = (const int*)  d_in[1];
    const float* qs   = (const float*)d_in[2];
    const float* bias = (const float*)d_in[3];
    const float* lA   = (const float*)d_in[4];
    const float* lB   = (const float*)d_in[5];
    float* out = (float*)d_out;

    cudaFuncSetAttribute(k_gemm, cudaFuncAttributeMaxDynamicSharedMemorySize, GEMM_SMEM);

    k_convert_x<<<4096, 256>>>(reinterpret_cast<const float4*>(x));
    k_fold_w<<<OUT_F / TO, 256>>>(qw, qs, lA, lB);
    k_gemm<<<dim3(OUT_F / BN, MTOT / BM), GEMM_THREADS, GEMM_SMEM>>>(bias, out);
}

// round 5
// speedup vs baseline: 1.0569x; 1.0357x over previous
#include <cuda_runtime.h>
#include <cuda_fp16.h>
#include <cstdint>
#include <cstddef>

#define IN_F   4096
#define OUT_F  4096
#define MTOT   8192   // 4 * 2048

// ---------------- scratch (static device globals: allocation-free) -----------
__device__ __half g_Xh[(size_t)MTOT * IN_F];   // x in fp16           (64 MiB)
__device__ __half g_Wh[(size_t)OUT_F * IN_F];  // W_eff in fp16       (32 MiB)

// ---------------- PTX helpers ----------------
__device__ __forceinline__ uint32_t smem_u32(const void* p) {
    uint32_t r;
    asm("{ .reg .u64 t; cvta.to.shared.u64 t, %1; cvt.u32.u64 %0, t; }"
        : "=r"(r) : "l"(p));
    return r;
}
__device__ __forceinline__ void cp_async16(uint32_t dst, const void* src) {
    asm volatile("cp.async.cg.shared.global [%0], [%1], 16;" :: "r"(dst), "l"(src));
}
#define CP_COMMIT() asm volatile("cp.async.commit_group;" ::: "memory")
#define CP_WAIT(n)  asm volatile("cp.async.wait_group %0;" :: "n"(n) : "memory")

__device__ __forceinline__ void ldsm_x4(uint32_t* r, uint32_t addr) {
    asm volatile("ldmatrix.sync.aligned.m8n8.x4.shared.b16 {%0,%1,%2,%3}, [%4];"
                 : "=r"(r[0]), "=r"(r[1]), "=r"(r[2]), "=r"(r[3]) : "r"(addr));
}
__device__ __forceinline__ void mma16816(float* c, const uint32_t* a, const uint32_t* b) {
    asm volatile(
        "mma.sync.aligned.m16n8k16.row.col.f32.f16.f16.f32 "
        "{%0,%1,%2,%3}, {%4,%5,%6,%7}, {%8,%9}, {%0,%1,%2,%3};"
        : "+f"(c[0]), "+f"(c[1]), "+f"(c[2]), "+f"(c[3])
        : "r"(a[0]), "r"(a[1]), "r"(a[2]), "r"(a[3]), "r"(b[0]), "r"(b[1]));
}

// ---------------- kernel 1: x fp32 -> fp16 ----------------
__global__ void k_convert_x(const float4* __restrict__ x) {
    const int n4 = MTOT * IN_F / 4;
    uint2* __restrict__ out = reinterpret_cast<uint2*>(g_Xh);
    int stride = gridDim.x * blockDim.x;
    for (int i = blockIdx.x * blockDim.x + threadIdx.x; i < n4; i += stride) {
        float4 v = x[i];
        __half2 lo = __floats2half2_rn(v.x, v.y);
        __half2 hi = __floats2half2_rn(v.z, v.w);
        uint2 o;
        o.x = *reinterpret_cast<uint32_t*>(&lo);
        o.y = *reinterpret_cast<uint32_t*>(&hi);
        out[i] = o;
    }
}

// ---------------- kernel 2: W_eff = dequant + LoRA fold -> fp16 --------------
#define TO 32
#define TI 512
__global__ void k_fold_w(const int* __restrict__ qw, const float* __restrict__ qs,
                         const float* __restrict__ A, const float* __restrict__ B) {
    __shared__ float As[16][TI + 4];
    __shared__ float Bs[TO][16];
    __shared__ float Ss[TO];
    const int tid = threadIdx.x;                  // 256
    const int o0 = blockIdx.x * TO;
    for (int t = tid; t < TO * 16; t += 256)
        Bs[t / 16][t % 16] = B[(size_t)(o0 + t / 16) * 16 + (t % 16)];
    if (tid < TO) Ss[tid] = qs[o0 + tid];
    const int ro = tid >> 3;    // row 0..31
    const int l8 = tid & 7;     // 0..7
    for (int cb = 0; cb < IN_F; cb += TI) {
        __syncthreads();
        for (int t = tid; t < 16 * (TI / 4); t += 256) {
            int r = t / (TI / 4), j = t % (TI / 4);
            float4 v = reinterpret_cast<const float4*>(A + (size_t)r * IN_F + cb)[j];
            *reinterpret_cast<float4*>(&As[r][j * 4]) = v;
        }
        __syncthreads();
        const float s = Ss[ro];
        const float* brow = Bs[ro];
        #pragma unroll 4
        for (int j = 0; j < TI / 32; ++j) {
            int il = l8 * 4 + j * 32;
            int4 q4 = *reinterpret_cast<const int4*>(&qw[(size_t)(o0 + ro) * IN_F + cb + il]);
            float a0 = q4.x * s, a1 = q4.y * s, a2 = q4.z * s, a3 = q4.w * s;
            #pragma unroll
            for (int r = 0; r < 16; ++r) {
                float b2 = 2.0f * brow[r];
                a0 = fmaf(b2, As[r][il + 0], a0);
                a1 = fmaf(b2, As[r][il + 1], a1);
                a2 = fmaf(b2, As[r][il + 2], a2);
                a3 = fmaf(b2, As[r][il + 3], a3);
            }
            __half2 h0 = __floats2half2_rn(a0, a1);
            __half2 h1 = __floats2half2_rn(a2, a3);
            uint2 o;
            o.x = *reinterpret_cast<uint32_t*>(&h0);
            o.y = *reinterpret_cast<uint32_t*>(&h1);
            *reinterpret_cast<uint2*>(&g_Wh[(size_t)(o0 + ro) * IN_F + cb + il]) = o;
        }
    }
}

// ---------------- kernel 3: pipelined mma.sync fp16 GEMM ----------------
// BM=128, BN=256, BKC=128 per pipeline chunk (two 64-wide halves), 2 stages.
// 16 warps as 2(m) x 8(n); warp tile 64x32; A-fragment ping-pong across ks.
#define BM 128
#define BN 256
#define BKC 128
#define NSTAGES 2
#define HALF_A (BM * 128)                   // 16384 (64 k-cols of A)
#define HALF_B (BN * 128)                   // 32768
#define HALF_BYTES (HALF_A + HALF_B)        // 49152
#define STAGE_BYTES (2 * HALF_BYTES)        // 98304
#define GEMM_SMEM (NSTAGES * STAGE_BYTES)   // 196608
#define GEMM_THREADS 512
#define KCH (IN_F / BKC)                    // 32

__device__ __forceinline__ void load_stage(uint32_t sb, int slot, int c,
                                           const __half* ga_base, const __half* gb_base,
                                           int tid) {
    uint32_t base = sb + slot * STAGE_BYTES;
    #pragma unroll
    for (int h = 0; h < 2; ++h) {
        uint32_t abase = base + h * HALF_BYTES;
        uint32_t bbase = abase + HALF_A;
        const __half* ga = ga_base + c * BKC + h * 64;
        const __half* gb = gb_base + c * BKC + h * 64;
        #pragma unroll
        for (int it = 0; it < (BM + BN) * 8 / GEMM_THREADS; ++it) {   // 6
            int t = tid + it * GEMM_THREADS;
            int chunk = t & 7;
            int row = (t >> 3);
            if (t < BM * 8) {
                uint32_t off = (uint32_t)(row * 128 + ((chunk ^ (row & 7)) << 4));
                cp_async16(abase + off, ga + (size_t)row * IN_F + chunk * 8);
            } else {
                row -= BM;
                uint32_t off = (uint32_t)(row * 128 + ((chunk ^ (row & 7)) << 4));
                cp_async16(bbase + off, gb + (size_t)row * IN_F + chunk * 8);
            }
        }
    }
}

__device__ __forceinline__ void lda_frags(uint32_t* af4x4, uint32_t stage_base,
                                          int ks, int wm, int lid) {
    uint32_t Ab = stage_base + (ks >> 2) * HALF_BYTES;
    int kk = ks & 3;
    #pragma unroll
    for (int i = 0; i < 4; ++i) {
        int row = wm * 64 + i * 16 + (lid & 15);
        int chunk = kk * 2 + (lid >> 4);
        uint32_t addr = Ab + (uint32_t)(row * 128) + (((chunk ^ (row & 7)) & 7) << 4);
        ldsm_x4(af4x4 + i * 4, addr);
    }
}

__global__ void __launch_bounds__(GEMM_THREADS, 1)
k_gemm(const float* __restrict__ bias, float* __restrict__ out) {
    extern __shared__ char smem[];
    uint32_t sb = smem_u32(smem);
    const int tid = threadIdx.x;
    const int wid = tid >> 5, lid = tid & 31;
    const int wm = wid & 1;          // 0..1  (m: 64-row halves)
    const int wn = wid >> 1;         // 0..7  (n: 32-col slices)
    const int m0 = blockIdx.y * BM;
    const int n0 = blockIdx.x * BN;
    const __half* ga_base = g_Xh + (size_t)m0 * IN_F;
    const __half* gb_base = g_Wh + (size_t)n0 * IN_F;

    float ac[4][4][4];
    #pragma unroll
    for (int i = 0; i < 4; ++i)
        #pragma unroll
        for (int j = 0; j < 4; ++j)
            #pragma unroll
            for (int k = 0; k < 4; ++k) ac[i][j][k] = 0.0f;

    // prologue: stage 0 <- chunk 0
    load_stage(sb, 0, 0, ga_base, gb_base, tid); CP_COMMIT();

    int slot = 0;
    for (int c = 0; c < KCH; ++c) {
        CP_WAIT(0);
        __syncthreads();
        if (c + 1 < KCH) {
            load_stage(sb, slot ^ 1, c + 1, ga_base, gb_base, tid);
            CP_COMMIT();
        }

        uint32_t stage_base = sb + slot * STAGE_BYTES;
        uint32_t af[2][16];
        lda_frags(af[0], stage_base, 0, wm, lid);

        #pragma unroll
        for (int ks = 0; ks < BKC / 16; ++ks) {          // 8
            int cur = ks & 1;
            // B fragments for this ks
            uint32_t Bb = stage_base + (ks >> 2) * HALF_BYTES + HALF_A;
            int kk = ks & 3;
            uint32_t bf[2][4];
            #pragma unroll
            for (int j = 0; j < 2; ++j) {
                int row = wn * 32 + j * 16 + ((lid >> 4) << 3) + (lid & 7);
                int chunk = kk * 2 + ((lid >> 3) & 1);
                uint32_t addr = Bb + (uint32_t)(row * 128) + (((chunk ^ (row & 7)) & 7) << 4);
                ldsm_x4(bf[j], addr);
            }
            // prefetch A fragments for next ks while MMAs run
            if (ks + 1 < BKC / 16)
                lda_frags(af[cur ^ 1], stage_base, ks + 1, wm, lid);
            #pragma unroll
            for (int i = 0; i < 4; ++i) {
                #pragma unroll
                for (int jj = 0; jj < 4; ++jj) {
                    mma16816(ac[i][jj], &af[cur][i * 4], &bf[jj >> 1][(jj & 1) * 2]);
                }
            }
        }
        slot ^= 1;
    }

    // epilogue: write 64x32 warp tile with bias
    const int mbase = m0 + wm * 64 + (lid >> 2);
    const int nbase = n0 + wn * 32 + (lid & 3) * 2;
    #pragma unroll
    for (int jj = 0; jj < 4; ++jj) {
        int n = nbase + jj * 8;
        float b0 = bias[n], b1 = bias[n + 1];
        #pragma unroll
        for (int i = 0; i < 4; ++i) {
            int m = mbase + i * 16;
            float2 v0 = make_float2(ac[i][jj][0] + b0, ac[i][jj][1] + b1);
            float2 v1 = make_float2(ac[i][jj][2] + b0, ac[i][jj][3] + b1);
            *reinterpret_cast<float2*>(&out[(size_t)m * OUT_F + n]) = v0;
            *reinterpret_cast<float2*>(&out[(size_t)(m + 8) * OUT_F + n]) = v1;
        }
    }
}

// ---------------- launcher ----------------
extern "C" void kernel_launch(void* const* d_in, const int* in_sizes, int n_in,
                              void* d_out, int out_size) {
    const float* x    = (const float*)d_in[0];
    const int*   qw   = (const int*)  d_in[1];
    const float* qs   = (const float*)d_in[2];
    const float* bias = (const float*)d_in[3];
    const float* lA   = (const float*)d_in[4];
    const float* lB   = (const float*)d_in[5];
    float* out = (float*)d_out;

    cudaFuncSetAttribute(k_gemm, cudaFuncAttributeMaxDynamicSharedMemorySize, GEMM_SMEM);

    k_convert_x<<<4096, 256>>>(reinterpret_cast<const float4*>(x));
    k_fold_w<<<OUT_F / TO, 256>>>(qw, qs, lA, lB);
    k_gemm<<<dim3(OUT_F / BN, MTOT / BM), GEMM_THREADS, GEMM_SMEM>>>(bias, out);
}